// round 1
// baseline (speedup 1.0000x reference)
#include <cuda_runtime.h>
#include <math.h>

#define BDIM 4096
#define INDIM 256
#define OUTDIM 256
#define NC 8
#define KDIM (INDIM * NC)   // 2048

// ---- scratch (no allocations allowed) ----
__device__ float g_DMT[KDIM * BDIM];   // A^T: [k][b]  (32 MB)
__device__ float g_W[KDIM * OUTDIM];   // B:   [k][o]  ( 2 MB)
__device__ float g_rv[BDIM];           // residual row sums
__device__ float g_r1[NC];
__device__ float g_r2[NC];
__device__ float g_alpha;

// ---------------------------------------------------------------------------
// 1) recurrence coefficients (depends on device scalar alpha_arctanh)
// ---------------------------------------------------------------------------
__global__ void prep_coeffs_kernel(const float* __restrict__ aat) {
    float a = tanhf(aat[0]);
    g_alpha = a;
    for (int n = 2; n < NC; n++) {
        float c  = 2.0f * n + 2.0f * a;               // 2n + alpha + beta
        float A  = 2.0f * n * (n + 2.0f * a) * (c - 2.0f);
        // alpha==beta  =>  alpha^2 - beta^2 == 0
        g_r1[n] = (c - 1.0f) * c * (c - 2.0f) / A;    // multiplies t*p[n-1]
        g_r2[n] = 2.0f * (n + a - 1.0f) * (n + a - 1.0f) * c / A; // multiplies p[n-2]
    }
}

// ---------------------------------------------------------------------------
// 2) W[k=i*8+c][o] = spline_scale[i,o] * coefs[i,o,c]
// ---------------------------------------------------------------------------
__global__ __launch_bounds__(256) void build_W_kernel(
    const float* __restrict__ coefs, const float* __restrict__ spline_scale) {
    int idx = blockIdx.x * 256 + threadIdx.x;   // idx = i*256 + o
    int i = idx >> 8;
    int o = idx & 255;
    float ss = spline_scale[idx];
    const float* cf = coefs + (size_t)idx * NC;
#pragma unroll
    for (int c = 0; c < NC; c++) {
        g_W[(i * NC + c) * OUTDIM + o] = ss * cf[c];
    }
}

// ---------------------------------------------------------------------------
// 3) DM^T[k][b] = P_c(tanh(x[b,i])),  rv[b] = sum_i resid_scale[i]*tanh(x[b,i])
//    one block per batch row b, 256 threads = one per input i
// ---------------------------------------------------------------------------
__global__ __launch_bounds__(256) void build_DM_kernel(
    const float* __restrict__ x, const float* __restrict__ resid_scale) {
    int b = blockIdx.x;
    int i = threadIdx.x;

    float t = tanhf(x[b * INDIM + i]);
    float a = g_alpha;

    float p[NC];
    p[0] = 1.0f;
    p[1] = (a + 1.0f) + (a + a + 2.0f) * (t - 1.0f) * 0.5f;
#pragma unroll
    for (int n = 2; n < NC; n++) {
        p[n] = g_r1[n] * t * p[n - 1] - g_r2[n] * p[n - 2];
    }

    // store K-major (coalesced over b across the warp per c)
#pragma unroll
    for (int c = 0; c < NC; c++) {
        g_DMT[(i * NC + c) * BDIM + b] = p[c];
    }

    // block reduction of resid_scale[i] * t  ->  rv[b]
    float rt = resid_scale[i] * t;
#pragma unroll
    for (int off = 16; off > 0; off >>= 1)
        rt += __shfl_down_sync(0xffffffffu, rt, off);

    __shared__ float sred[8];
    if ((i & 31) == 0) sred[i >> 5] = rt;
    __syncthreads();
    if (i < 8) {
        float v = sred[i];
#pragma unroll
        for (int off = 4; off > 0; off >>= 1)
            v += __shfl_down_sync(0xffu, v, off);
        if (i == 0) g_rv[b] = v;
    }
}

// ---------------------------------------------------------------------------
// 4) GEMM: out[b][o] = (rv[b] + sum_k DMT[k][b] * W[k][o]) / 256
//    64x64 tile, BK=16, 4x4 per thread, 256 threads, double-buffered smem
// ---------------------------------------------------------------------------
#define BM 64
#define BN 64
#define BK 16
#define TM 4
#define TN 4

__global__ __launch_bounds__(256) void gemm_kernel(float* __restrict__ out) {
    __shared__ float As[2][BK][BM];
    __shared__ float Bs[2][BK][BN];

    const int tid = threadIdx.x;
    const int tx  = tid & 15;    // N direction (16)
    const int ty  = tid >> 4;    // M direction (16)
    const int m0  = blockIdx.x * BM;
    const int n0  = blockIdx.y * BN;

    // tile-load mapping: row within BK, 4-wide column chunk
    const int lk  = tid >> 4;          // 0..15
    const int lc4 = (tid & 15) * 4;    // 0,4,...,60

    float acc[TM][TN];
#pragma unroll
    for (int r = 0; r < TM; r++)
#pragma unroll
        for (int c = 0; c < TN; c++) acc[r][c] = 0.0f;

    const int NT = KDIM / BK;   // 128 k-tiles

    // preload tile 0
    {
        float4 ra = *(const float4*)&g_DMT[(0 * BK + lk) * BDIM + m0 + lc4];
        float4 rb = *(const float4*)&g_W  [(0 * BK + lk) * OUTDIM + n0 + lc4];
        *(float4*)&As[0][lk][lc4] = ra;
        *(float4*)&Bs[0][lk][lc4] = rb;
    }
    __syncthreads();

    int cur = 0;
    for (int kt = 0; kt < NT; kt++) {
        float4 ra, rb;
        const bool has_next = (kt + 1) < NT;
        if (has_next) {
            ra = *(const float4*)&g_DMT[((kt + 1) * BK + lk) * BDIM + m0 + lc4];
            rb = *(const float4*)&g_W  [((kt + 1) * BK + lk) * OUTDIM + n0 + lc4];
        }

#pragma unroll
        for (int kk = 0; kk < BK; kk++) {
            float4 av = *(const float4*)&As[cur][kk][ty * TM];
            float4 bv = *(const float4*)&Bs[cur][kk][tx * TN];
            acc[0][0] += av.x * bv.x; acc[0][1] += av.x * bv.y;
            acc[0][2] += av.x * bv.z; acc[0][3] += av.x * bv.w;
            acc[1][0] += av.y * bv.x; acc[1][1] += av.y * bv.y;
            acc[1][2] += av.y * bv.z; acc[1][3] += av.y * bv.w;
            acc[2][0] += av.z * bv.x; acc[2][1] += av.z * bv.y;
            acc[2][2] += av.z * bv.z; acc[2][3] += av.z * bv.w;
            acc[3][0] += av.w * bv.x; acc[3][1] += av.w * bv.y;
            acc[3][2] += av.w * bv.z; acc[3][3] += av.w * bv.w;
        }

        if (has_next) {
            *(float4*)&As[cur ^ 1][lk][lc4] = ra;
            *(float4*)&Bs[cur ^ 1][lk][lc4] = rb;
        }
        __syncthreads();
        cur ^= 1;
    }

    // epilogue: add residual row term, scale by 1/IN, vectorized store
    const float inv_in = 1.0f / (float)INDIM;
#pragma unroll
    for (int r = 0; r < TM; r++) {
        int m = m0 + ty * TM + r;
        float rv = g_rv[m];
        float4 v;
        v.x = (acc[r][0] + rv) * inv_in;
        v.y = (acc[r][1] + rv) * inv_in;
        v.z = (acc[r][2] + rv) * inv_in;
        v.w = (acc[r][3] + rv) * inv_in;
        *(float4*)&out[(size_t)m * OUTDIM + n0 + tx * TN] = v;
    }
}

// ---------------------------------------------------------------------------
extern "C" void kernel_launch(void* const* d_in, const int* in_sizes, int n_in,
                              void* d_out, int out_size) {
    // robust input mapping by (distinct) element counts
    const float *x = nullptr, *coefs = nullptr, *aat = nullptr;
    const float *resid_scale = nullptr, *spline_scale = nullptr;
    for (int i = 0; i < n_in; i++) {
        switch (in_sizes[i]) {
            case BDIM * INDIM:        x            = (const float*)d_in[i]; break; // 1048576
            case INDIM * OUTDIM * NC: coefs        = (const float*)d_in[i]; break; // 524288
            case 1:                   aat          = (const float*)d_in[i]; break;
            case INDIM:               resid_scale  = (const float*)d_in[i]; break; // 256
            case INDIM * OUTDIM:      spline_scale = (const float*)d_in[i]; break; // 65536
            default: break;
        }
    }
    float* out = (float*)d_out;

    prep_coeffs_kernel<<<1, 1>>>(aat);
    build_W_kernel<<<(INDIM * OUTDIM) / 256, 256>>>(coefs, spline_scale);
    build_DM_kernel<<<BDIM, 256>>>(x, resid_scale);
    dim3 grid(BDIM / BM, OUTDIM / BN);
    gemm_kernel<<<grid, 256>>>(out);
}

// round 3
// speedup vs baseline: 2.5842x; 2.5842x over previous
#include <cuda_runtime.h>
#include <cuda_bf16.h>
#include <cstdint>
#include <math.h>

#define BDIM   4096
#define INDIM  256
#define OUTDIM 256
#define NC     8
#define KDIM   (INDIM * NC)      // 2048

// ---------------- scratch (static device globals; no allocations) ----------
__device__ __nv_bfloat16 g_Ah[(size_t)BDIM * KDIM];   // 16 MB  A hi, [b][k]
__device__ __nv_bfloat16 g_Al[(size_t)BDIM * KDIM];   // 16 MB  A lo
__device__ __nv_bfloat16 g_Bh[(size_t)OUTDIM * KDIM]; //  1 MB  B hi, [o][k]
__device__ __nv_bfloat16 g_Bl[(size_t)OUTDIM * KDIM]; //  1 MB  B lo
__device__ float g_rv[BDIM];
__device__ float g_r1[NC], g_r2[NC], g_alphaD;

// ---------------------------------------------------------------------------
// 1) recurrence coefficients
// ---------------------------------------------------------------------------
__global__ void prep_coeffs_kernel(const float* __restrict__ aat) {
    float a = tanhf(aat[0]);
    g_alphaD = a;
    for (int n = 2; n < NC; n++) {
        float c = 2.0f * n + 2.0f * a;
        float A = 2.0f * n * (n + 2.0f * a) * (c - 2.0f);
        g_r1[n] = (c - 1.0f) * c * (c - 2.0f) / A;   // alpha==beta
        g_r2[n] = 2.0f * (n + a - 1.0f) * (n + a - 1.0f) * c / A;
    }
}

// ---------------------------------------------------------------------------
// 2) B = W^T hi/lo:  g_B*[o][i*8+c] = hi/lo( spline_scale[i,o] * coefs[i,o,c] )
// ---------------------------------------------------------------------------
__global__ __launch_bounds__(256) void build_W_kernel(
    const float* __restrict__ coefs, const float* __restrict__ spline_scale) {
    int idx = blockIdx.x * 256 + threadIdx.x;  // i*256 + o
    int i = idx >> 8, o = idx & 255;
    float ss = spline_scale[idx];
    const float* cf = coefs + (size_t)idx * NC;
    float h[NC], l[NC];
#pragma unroll
    for (int c = 0; c < NC; c++) {
        float v = ss * cf[c];
        __nv_bfloat16 hb = __float2bfloat16(v);
        h[c] = __bfloat162float(hb);
        l[c] = v - h[c];
    }
    uint4 uh, ul;
    {
        __nv_bfloat162 t;
        uint32_t* ph = (uint32_t*)&uh;
        uint32_t* pl = (uint32_t*)&ul;
#pragma unroll
        for (int c = 0; c < 4; c++) {
            t = __floats2bfloat162_rn(h[2 * c], h[2 * c + 1]); ph[c] = *(uint32_t*)&t;
            t = __floats2bfloat162_rn(l[2 * c], l[2 * c + 1]); pl[c] = *(uint32_t*)&t;
        }
    }
    *(uint4*)&g_Bh[(size_t)o * KDIM + i * NC] = uh;
    *(uint4*)&g_Bl[(size_t)o * KDIM + i * NC] = ul;
}

// ---------------------------------------------------------------------------
// 3) A = DM hi/lo row-major [b][k] + rv[b]
// ---------------------------------------------------------------------------
__global__ __launch_bounds__(256) void build_AB_kernel(
    const float* __restrict__ x, const float* __restrict__ resid_scale) {
    int b = blockIdx.x;
    int i = threadIdx.x;
    float t = tanhf(x[b * INDIM + i]);
    float a = g_alphaD;

    float p[NC];
    p[0] = 1.0f;
    p[1] = (a + 1.0f) + (a + a + 2.0f) * (t - 1.0f) * 0.5f;
#pragma unroll
    for (int n = 2; n < NC; n++)
        p[n] = g_r1[n] * t * p[n - 1] - g_r2[n] * p[n - 2];

    float h[NC], l[NC];
#pragma unroll
    for (int c = 0; c < NC; c++) {
        __nv_bfloat16 hb = __float2bfloat16(p[c]);
        h[c] = __bfloat162float(hb);
        l[c] = p[c] - h[c];
    }
    uint4 uh, ul;
    {
        __nv_bfloat162 tt;
        uint32_t* ph = (uint32_t*)&uh;
        uint32_t* pl = (uint32_t*)&ul;
#pragma unroll
        for (int c = 0; c < 4; c++) {
            tt = __floats2bfloat162_rn(h[2 * c], h[2 * c + 1]); ph[c] = *(uint32_t*)&tt;
            tt = __floats2bfloat162_rn(l[2 * c], l[2 * c + 1]); pl[c] = *(uint32_t*)&tt;
        }
    }
    *(uint4*)&g_Ah[(size_t)b * KDIM + i * NC] = uh;
    *(uint4*)&g_Al[(size_t)b * KDIM + i * NC] = ul;

    float rt = resid_scale[i] * t;
#pragma unroll
    for (int off = 16; off > 0; off >>= 1)
        rt += __shfl_down_sync(0xffffffffu, rt, off);
    __shared__ float sred[8];
    if ((i & 31) == 0) sred[i >> 5] = rt;
    __syncthreads();
    if (i < 8) {
        float v = sred[i];
#pragma unroll
        for (int off = 4; off > 0; off >>= 1)
            v += __shfl_down_sync(0xffu, v, off);
        if (i == 0) g_rv[b] = v;
    }
}

// ---------------------------------------------------------------------------
// 4) mma.sync bf16 GEMM, 3-pass hi/lo fp32 emulation
//    CTA 128x64, BK=32, 8 warps (warp tile 32x32), cp.async double buffer
// ---------------------------------------------------------------------------
#define BM 128
#define BN 64
#define BK 32
#define NT (KDIM / BK)          // 64 k-chunks

#define ROWB 80                 // padded row stride in bytes (64 data + 16 pad)
#define A_TILE_B (BM * ROWB)    // 10240
#define B_TILE_B (BN * ROWB)    //  5120
#define STAGE_B (2 * A_TILE_B + 2 * B_TILE_B)   // 30720
// stage layout: Ah @0, Al @A_TILE_B, Bh @2*A_TILE_B, Bl @2*A_TILE_B+B_TILE_B
#define GEMM_SMEM (2 * STAGE_B)                 // 61440

__device__ __forceinline__ uint32_t smem_u32(const void* p) {
    uint32_t a;
    asm("{ .reg .u64 t; cvta.to.shared.u64 t, %1; cvt.u32.u64 %0, t; }"
        : "=r"(a) : "l"(p));
    return a;
}
__device__ __forceinline__ void cp16(uint32_t s, const void* g) {
    asm volatile("cp.async.cg.shared.global [%0], [%1], 16;" :: "r"(s), "l"(g));
}
__device__ __forceinline__ void ldsm_x4(uint32_t* r, uint32_t addr) {
    asm volatile("ldmatrix.sync.aligned.m8n8.x4.shared.b16 {%0,%1,%2,%3}, [%4];"
                 : "=r"(r[0]), "=r"(r[1]), "=r"(r[2]), "=r"(r[3]) : "r"(addr));
}
__device__ __forceinline__ void mma_bf16(float* d, const uint32_t* a, const uint32_t* b) {
    asm volatile(
        "mma.sync.aligned.m16n8k16.row.col.f32.bf16.bf16.f32 "
        "{%0,%1,%2,%3}, {%4,%5,%6,%7}, {%8,%9}, {%0,%1,%2,%3};"
        : "+f"(d[0]), "+f"(d[1]), "+f"(d[2]), "+f"(d[3])
        : "r"(a[0]), "r"(a[1]), "r"(a[2]), "r"(a[3]), "r"(b[0]), "r"(b[1]));
}

__device__ __forceinline__ void prefetch_stage(uint32_t sbase, int kt,
                                               int m0, int n0, int tid) {
    int k0 = kt * BK;
    // A tiles: 128 rows x 4 chunks of 16B = 512 chunks; 2 per thread
#pragma unroll
    for (int it = 0; it < 2; ++it) {
        int idx = it * 256 + tid;
        int r = idx >> 2, c = idx & 3;
        uint32_t so = sbase + r * ROWB + c * 16;
        size_t go = (size_t)(m0 + r) * KDIM + k0 + c * 8;
        cp16(so, g_Ah + go);
        cp16(so + A_TILE_B, g_Al + go);
    }
    // B tiles: 64 rows x 4 chunks = 256 chunks; 1 per thread
    {
        int r = tid >> 2, c = tid & 3;
        uint32_t so = sbase + 2 * A_TILE_B + r * ROWB + c * 16;
        size_t go = (size_t)(n0 + r) * KDIM + k0 + c * 8;
        cp16(so, g_Bh + go);
        cp16(so + B_TILE_B, g_Bl + go);
    }
    asm volatile("cp.async.commit_group;" ::: "memory");
}

__global__ __launch_bounds__(256, 1) void gemm_mma(float* __restrict__ out) {
    extern __shared__ char smem[];
    const int tid  = threadIdx.x;
    const int wid  = tid >> 5;
    const int lane = tid & 31;
    const int m0   = blockIdx.x * BM;
    const int n0   = blockIdx.y * BN;
    const int mbase = (wid & 3) * 32;   // warp tile m (4 warps)
    const int nbase = (wid >> 2) * 32;  // warp tile n (2 warps)
    const uint32_t sb = smem_u32(smem);

    float acc[2][4][4];
#pragma unroll
    for (int i = 0; i < 2; i++)
#pragma unroll
        for (int j = 0; j < 4; j++)
#pragma unroll
            for (int r = 0; r < 4; r++) acc[i][j][r] = 0.0f;

    // per-lane ldmatrix address pieces
    const int g  = lane >> 3;          // address group
    const int lr = lane & 7;
    const int a_row_off = lr + ((g & 1) ? 8 : 0);   // within 16-row frag
    const int kb_off    = (g >= 2) ? 16 : 0;        // within 32B k-step

    prefetch_stage(sb, 0, m0, n0, tid);

    for (int kt = 0; kt < NT; ++kt) {
        if (kt + 1 < NT) {
            prefetch_stage(sb + ((kt + 1) & 1) * STAGE_B, kt + 1, m0, n0, tid);
            asm volatile("cp.async.wait_group 1;" ::: "memory");
        } else {
            asm volatile("cp.async.wait_group 0;" ::: "memory");
        }
        __syncthreads();

        const uint32_t st = sb + (kt & 1) * STAGE_B;
#pragma unroll
        for (int ks = 0; ks < 2; ++ks) {
            const uint32_t kbyte = ks * 32 + kb_off;
            uint32_t ah[2][4], al[2][4], bh[4][2], bl[4][2];
#pragma unroll
            for (int mf = 0; mf < 2; ++mf) {
                uint32_t row = mbase + mf * 16 + a_row_off;
                uint32_t ad = st + row * ROWB + kbyte;
                ldsm_x4(ah[mf], ad);
                ldsm_x4(al[mf], ad + A_TILE_B);
            }
#pragma unroll
            for (int np = 0; np < 2; ++np) {
                // groups: g0: n rows 0-7 @kb, g1: rows 0-7 @kb+16, g2: rows 8-15 @kb, g3: +16
                uint32_t row = nbase + np * 16 + lr + ((g >= 2) ? 8 : 0);
                uint32_t kb2 = ks * 32 + ((g & 1) ? 16 : 0);
                uint32_t bd = st + 2 * A_TILE_B + row * ROWB + kb2;
                uint32_t r4[4];
                ldsm_x4(r4, bd);
                bh[2 * np][0] = r4[0]; bh[2 * np][1] = r4[1];
                bh[2 * np + 1][0] = r4[2]; bh[2 * np + 1][1] = r4[3];
                ldsm_x4(r4, bd + B_TILE_B);
                bl[2 * np][0] = r4[0]; bl[2 * np][1] = r4[1];
                bl[2 * np + 1][0] = r4[2]; bl[2 * np + 1][1] = r4[3];
            }
#pragma unroll
            for (int mf = 0; mf < 2; ++mf)
#pragma unroll
                for (int nf = 0; nf < 4; ++nf) {
                    mma_bf16(acc[mf][nf], ah[mf], bh[nf]);
                    mma_bf16(acc[mf][nf], ah[mf], bl[nf]);
                    mma_bf16(acc[mf][nf], al[mf], bh[nf]);
                }
        }
        __syncthreads();
    }

    // epilogue: out[m][n] = (acc + rv[m]) / 256
    const float s = 1.0f / (float)INDIM;
    const int l4 = lane >> 2, l2 = (lane & 3) * 2;
#pragma unroll
    for (int mf = 0; mf < 2; ++mf) {
        int m = m0 + mbase + mf * 16 + l4;
        float rv0 = g_rv[m];
        float rv1 = g_rv[m + 8];
#pragma unroll
        for (int nf = 0; nf < 4; ++nf) {
            int n = n0 + nbase + nf * 8 + l2;
            float2 v0 = make_float2((acc[mf][nf][0] + rv0) * s,
                                    (acc[mf][nf][1] + rv0) * s);
            float2 v1 = make_float2((acc[mf][nf][2] + rv1) * s,
                                    (acc[mf][nf][3] + rv1) * s);
            *(float2*)&out[(size_t)m * OUTDIM + n] = v0;
            *(float2*)&out[(size_t)(m + 8) * OUTDIM + n] = v1;
        }
    }
}

// ---------------------------------------------------------------------------
extern "C" void kernel_launch(void* const* d_in, const int* in_sizes, int n_in,
                              void* d_out, int out_size) {
    const float *x = nullptr, *coefs = nullptr, *aat = nullptr;
    const float *resid_scale = nullptr, *spline_scale = nullptr;
    for (int i = 0; i < n_in; i++) {
        switch (in_sizes[i]) {
            case BDIM * INDIM:        x            = (const float*)d_in[i]; break;
            case INDIM * OUTDIM * NC: coefs        = (const float*)d_in[i]; break;
            case 1:                   aat          = (const float*)d_in[i]; break;
            case INDIM:               resid_scale  = (const float*)d_in[i]; break;
            case INDIM * OUTDIM:      spline_scale = (const float*)d_in[i]; break;
            default: break;
        }
    }
    float* out = (float*)d_out;

    cudaFuncSetAttribute(gemm_mma, cudaFuncAttributeMaxDynamicSharedMemorySize, GEMM_SMEM);

    prep_coeffs_kernel<<<1, 1>>>(aat);
    build_W_kernel<<<(INDIM * OUTDIM) / 256, 256>>>(coefs, spline_scale);
    build_AB_kernel<<<BDIM, 256>>>(x, resid_scale);
    dim3 grid(BDIM / BM, OUTDIM / BN);
    gemm_mma<<<grid, 256, GEMM_SMEM>>>(out);
}

// round 4
// speedup vs baseline: 2.7888x; 1.0792x over previous
#include <cuda_runtime.h>
#include <cuda_bf16.h>
#include <cstdint>
#include <math.h>

#define BDIM   4096
#define INDIM  256
#define OUTDIM 256
#define NC     8
#define KDIM   (INDIM * NC)      // 2048

// ---------------- scratch (static device globals; no allocations) ----------
__device__ __nv_bfloat16 g_Bh[(size_t)OUTDIM * KDIM]; //  1 MB  B hi, [o][k]
__device__ __nv_bfloat16 g_Bl[(size_t)OUTDIM * KDIM]; //  1 MB  B lo
__device__ float g_r1[NC], g_r2[NC], g_alphaD;

// ---------------------------------------------------------------------------
// 1) recurrence coefficients
// ---------------------------------------------------------------------------
__global__ void prep_coeffs_kernel(const float* __restrict__ aat) {
    float a = tanhf(aat[0]);
    g_alphaD = a;
    for (int n = 2; n < NC; n++) {
        float c = 2.0f * n + 2.0f * a;
        float A = 2.0f * n * (n + 2.0f * a) * (c - 2.0f);
        g_r1[n] = (c - 1.0f) * c * (c - 2.0f) / A;   // alpha==beta
        g_r2[n] = 2.0f * (n + a - 1.0f) * (n + a - 1.0f) * c / A;
    }
}

// ---------------------------------------------------------------------------
// 2) B = W^T hi/lo:  g_B*[o][i*8+c] = hi/lo( spline_scale[i,o] * coefs[i,o,c] )
// ---------------------------------------------------------------------------
__global__ __launch_bounds__(256) void build_W_kernel(
    const float* __restrict__ coefs, const float* __restrict__ spline_scale) {
    int idx = blockIdx.x * 256 + threadIdx.x;  // i*256 + o
    int i = idx >> 8, o = idx & 255;
    float ss = spline_scale[idx];
    const float* cf = coefs + (size_t)idx * NC;
    float h[NC], l[NC];
#pragma unroll
    for (int c = 0; c < NC; c++) {
        float v = ss * cf[c];
        __nv_bfloat16 hb = __float2bfloat16(v);
        h[c] = __bfloat162float(hb);
        l[c] = v - h[c];
    }
    uint4 uh, ul;
    {
        __nv_bfloat162 t;
        uint32_t* ph = (uint32_t*)&uh;
        uint32_t* pl = (uint32_t*)&ul;
#pragma unroll
        for (int c = 0; c < 4; c++) {
            t = __floats2bfloat162_rn(h[2 * c], h[2 * c + 1]); ph[c] = *(uint32_t*)&t;
            t = __floats2bfloat162_rn(l[2 * c], l[2 * c + 1]); pl[c] = *(uint32_t*)&t;
        }
    }
    *(uint4*)&g_Bh[(size_t)o * KDIM + i * NC] = uh;
    *(uint4*)&g_Bl[(size_t)o * KDIM + i * NC] = ul;
}

// ---------------------------------------------------------------------------
// 3) fused GEMM: CTA 64x64, BK=64, 128 threads (4 warps, warp tile 32x32)
//    A tile computed in-kernel (tanh -> Jacobi -> hi/lo), B via cp.async.
//    3-pass hi/lo bf16 emulation of fp32.
// ---------------------------------------------------------------------------
#define BM 64
#define BN 64
#define BK 64
#define NT (KDIM / BK)          // 32 k-chunks

#define ROWB 144                // 128B data + 16B pad
#define TILE_B (64 * ROWB)      // 9216 per tile
// stage layout: Ah @0, Al @TILE_B, Bh @2*TILE_B, Bl @3*TILE_B
#define STAGE_B (4 * TILE_B)    // 36864
#define GEMM_SMEM (2 * STAGE_B) // 73728

__device__ __forceinline__ uint32_t smem_u32(const void* p) {
    uint32_t a;
    asm("{ .reg .u64 t; cvta.to.shared.u64 t, %1; cvt.u32.u64 %0, t; }"
        : "=r"(a) : "l"(p));
    return a;
}
__device__ __forceinline__ void cp16(uint32_t s, const void* g) {
    asm volatile("cp.async.cg.shared.global [%0], [%1], 16;" :: "r"(s), "l"(g));
}
__device__ __forceinline__ void ldsm_x4(uint32_t* r, uint32_t addr) {
    asm volatile("ldmatrix.sync.aligned.m8n8.x4.shared.b16 {%0,%1,%2,%3}, [%4];"
                 : "=r"(r[0]), "=r"(r[1]), "=r"(r[2]), "=r"(r[3]) : "r"(addr));
}
__device__ __forceinline__ void mma_bf16(float* d, const uint32_t* a, const uint32_t* b) {
    asm volatile(
        "mma.sync.aligned.m16n8k16.row.col.f32.bf16.bf16.f32 "
        "{%0,%1,%2,%3}, {%4,%5,%6,%7}, {%8,%9}, {%0,%1,%2,%3};"
        : "+f"(d[0]), "+f"(d[1]), "+f"(d[2]), "+f"(d[3])
        : "r"(a[0]), "r"(a[1]), "r"(a[2]), "r"(a[3]), "r"(b[0]), "r"(b[1]));
}

// B prefetch: Bh/Bl, 64 rows x 128B each -> 1024 x 16B chunks / 128 threads
__device__ __forceinline__ void prefetch_B(uint32_t sbase, int kt, int n0, int tid) {
    int k0 = kt * BK;
#pragma unroll
    for (int p = 0; p < 4; ++p) {
        int idx = p * 128 + tid;           // 0..511
        int r = idx >> 3, c = idx & 7;
        uint32_t so = sbase + 2 * TILE_B + r * ROWB + c * 16;
        size_t go = (size_t)(n0 + r) * KDIM + k0 + c * 8;
        cp16(so, g_Bh + go);
        cp16(so + TILE_B, g_Bl + go);
    }
    asm volatile("cp.async.commit_group;" ::: "memory");
}

// A compute: 64 rows x 8 i-values per stage; thread handles 4 (b,i) pairs
__device__ __forceinline__ void compute_A(
    char* abase, int kt, int m0, const float* __restrict__ x,
    const float* __restrict__ resid_scale, float* rv_acc,
    float alpha, const float* r1, const float* r2, int tid) {
    const int il = tid & 7;
    const int i  = kt * 8 + il;
    const float rs = resid_scale[i];
#pragma unroll
    for (int p = 0; p < 4; ++p) {
        int b = p * 16 + (tid >> 3);
        float t = tanhf(x[(size_t)(m0 + b) * INDIM + i]);
        rv_acc[p] += rs * t;

        float pr[NC];
        pr[0] = 1.0f;
        pr[1] = (alpha + 1.0f) + (alpha + alpha + 2.0f) * (t - 1.0f) * 0.5f;
#pragma unroll
        for (int n = 2; n < NC; n++)
            pr[n] = r1[n] * t * pr[n - 1] - r2[n] * pr[n - 2];

        uint4 uh, ul;
        uint32_t* ph = (uint32_t*)&uh;
        uint32_t* pl = (uint32_t*)&ul;
#pragma unroll
        for (int c = 0; c < 4; c++) {
            float h0, h1, l0, l1;
            __nv_bfloat16 hb;
            hb = __float2bfloat16(pr[2 * c]);     h0 = __bfloat162float(hb); l0 = pr[2 * c] - h0;
            hb = __float2bfloat16(pr[2 * c + 1]); h1 = __bfloat162float(hb); l1 = pr[2 * c + 1] - h1;
            __nv_bfloat162 t2;
            t2 = __floats2bfloat162_rn(h0, h1); ph[c] = *(uint32_t*)&t2;
            t2 = __floats2bfloat162_rn(l0, l1); pl[c] = *(uint32_t*)&t2;
        }
        char* dst = abase + b * ROWB + il * 16;
        *(uint4*)dst = uh;
        *(uint4*)(dst + TILE_B) = ul;
    }
}

__global__ __launch_bounds__(128, 3) void gemm_fused(
    float* __restrict__ out, const float* __restrict__ x,
    const float* __restrict__ resid_scale) {
    extern __shared__ char smem[];
    __shared__ float s_rv[BM];

    const int tid  = threadIdx.x;
    const int wid  = tid >> 5;
    const int lane = tid & 31;
    const int m0   = blockIdx.x * BM;
    const int n0   = blockIdx.y * BN;
    const int mbase = (wid & 1) * 32;
    const int nbase = (wid >> 1) * 32;
    const uint32_t sb = smem_u32(smem);

    // recurrence coefficients into registers
    const float alpha = g_alphaD;
    float r1[NC], r2[NC];
#pragma unroll
    for (int n = 2; n < NC; n++) { r1[n] = g_r1[n]; r2[n] = g_r2[n]; }

    float acc[2][4][4];
#pragma unroll
    for (int i = 0; i < 2; i++)
#pragma unroll
        for (int j = 0; j < 4; j++)
#pragma unroll
            for (int r = 0; r < 4; r++) acc[i][j][r] = 0.0f;
    float rv_acc[4] = {0.f, 0.f, 0.f, 0.f};

    // ldmatrix per-lane address pieces (same mapping as R3, verified)
    const int g  = lane >> 3;
    const int lr = lane & 7;
    const int a_row_off = lr + ((g & 1) ? 8 : 0);
    const int kb_off    = (g >= 2) ? 16 : 0;

    // prologue
    compute_A(smem, 0, m0, x, resid_scale, rv_acc, alpha, r1, r2, tid);
    prefetch_B(sb, 0, n0, tid);
    if (NT > 1) prefetch_B(sb + STAGE_B, 1, n0, tid);
    asm volatile("cp.async.wait_group 1;" ::: "memory");
    __syncthreads();

    for (int kt = 0; kt < NT; ++kt) {
        const int s = kt & 1;
        const uint32_t st = sb + s * STAGE_B;

        // ---- MMA over stage s ----
#pragma unroll
        for (int ks = 0; ks < 4; ++ks) {
            const uint32_t kbyte = ks * 32 + kb_off;
            uint32_t ah[2][4], al[2][4], bh[4][2], bl[4][2];
#pragma unroll
            for (int mf = 0; mf < 2; ++mf) {
                uint32_t row = mbase + mf * 16 + a_row_off;
                uint32_t ad = st + row * ROWB + kbyte;
                ldsm_x4(ah[mf], ad);
                ldsm_x4(al[mf], ad + TILE_B);
            }
#pragma unroll
            for (int np = 0; np < 2; ++np) {
                uint32_t row = nbase + np * 16 + lr + ((g >= 2) ? 8 : 0);
                uint32_t kb2 = ks * 32 + ((g & 1) ? 16 : 0);
                uint32_t bd = st + 2 * TILE_B + row * ROWB + kb2;
                uint32_t r4[4];
                ldsm_x4(r4, bd);
                bh[2 * np][0] = r4[0];     bh[2 * np][1] = r4[1];
                bh[2 * np + 1][0] = r4[2]; bh[2 * np + 1][1] = r4[3];
                ldsm_x4(r4, bd + TILE_B);
                bl[2 * np][0] = r4[0];     bl[2 * np][1] = r4[1];
                bl[2 * np + 1][0] = r4[2]; bl[2 * np + 1][1] = r4[3];
            }
#pragma unroll
            for (int mf = 0; mf < 2; ++mf)
#pragma unroll
                for (int nf = 0; nf < 4; ++nf) {
                    mma_bf16(acc[mf][nf], ah[mf], bh[nf]);
                    mma_bf16(acc[mf][nf], ah[mf], bl[nf]);
                    mma_bf16(acc[mf][nf], al[mf], bh[nf]);
                }
        }
        __syncthreads();   // all warps done reading stage s

        if (kt + 1 < NT) {
            // A(kt+1) into stage s^1 (its A region last read at kt-1; safe)
            compute_A(smem + (s ^ 1) * STAGE_B, kt + 1, m0, x, resid_scale,
                      rv_acc, alpha, r1, r2, tid);
            // B(kt+2) into stage s (B region of s read this iter; safe)
            if (kt + 2 < NT) prefetch_B(st, kt + 2, n0, tid);
            if (kt + 2 < NT) {
                asm volatile("cp.async.wait_group 1;" ::: "memory");
            } else {
                asm volatile("cp.async.wait_group 0;" ::: "memory");
            }
            __syncthreads();   // A(kt+1) visible; B(kt+1) arrived
        }
    }

    // rv reduction: 8 lanes (same b-group) per value
#pragma unroll
    for (int p = 0; p < 4; ++p) {
        float v = rv_acc[p];
        v += __shfl_xor_sync(0xffffffffu, v, 1);
        v += __shfl_xor_sync(0xffffffffu, v, 2);
        v += __shfl_xor_sync(0xffffffffu, v, 4);
        if ((lane & 7) == 0) s_rv[p * 16 + (tid >> 3)] = v;
    }
    __syncthreads();

    // epilogue: out[m][n] = (acc + rv[m]) / 256
    const float sc = 1.0f / (float)INDIM;
    const int l4 = lane >> 2, l2 = (lane & 3) * 2;
#pragma unroll
    for (int mf = 0; mf < 2; ++mf) {
        int ml = mbase + mf * 16 + l4;
        int m = m0 + ml;
        float rv0 = s_rv[ml];
        float rv1 = s_rv[ml + 8];
#pragma unroll
        for (int nf = 0; nf < 4; ++nf) {
            int n = n0 + nbase + nf * 8 + l2;
            float2 v0 = make_float2((acc[mf][nf][0] + rv0) * sc,
                                    (acc[mf][nf][1] + rv0) * sc);
            float2 v1 = make_float2((acc[mf][nf][2] + rv1) * sc,
                                    (acc[mf][nf][3] + rv1) * sc);
            *(float2*)&out[(size_t)m * OUTDIM + n] = v0;
            *(float2*)&out[(size_t)(m + 8) * OUTDIM + n] = v1;
        }
    }
}

// ---------------------------------------------------------------------------
extern "C" void kernel_launch(void* const* d_in, const int* in_sizes, int n_in,
                              void* d_out, int out_size) {
    const float *x = nullptr, *coefs = nullptr, *aat = nullptr;
    const float *resid_scale = nullptr, *spline_scale = nullptr;
    for (int i = 0; i < n_in; i++) {
        switch (in_sizes[i]) {
            case BDIM * INDIM:        x            = (const float*)d_in[i]; break;
            case INDIM * OUTDIM * NC: coefs        = (const float*)d_in[i]; break;
            case 1:                   aat          = (const float*)d_in[i]; break;
            case INDIM:               resid_scale  = (const float*)d_in[i]; break;
            case INDIM * OUTDIM:      spline_scale = (const float*)d_in[i]; break;
            default: break;
        }
    }
    float* out = (float*)d_out;

    cudaFuncSetAttribute(gemm_fused, cudaFuncAttributeMaxDynamicSharedMemorySize, GEMM_SMEM);

    prep_coeffs_kernel<<<1, 1>>>(aat);
    build_W_kernel<<<(INDIM * OUTDIM) / 256, 256>>>(coefs, spline_scale);
    dim3 grid(BDIM / BM, OUTDIM / BN);
    gemm_fused<<<grid, 128, GEMM_SMEM>>>(out, x, resid_scale);
}

// round 6
// speedup vs baseline: 5.5079x; 1.9750x over previous
#include <cuda_runtime.h>
#include <cuda_bf16.h>
#include <cstdint>
#include <math.h>

#define BDIM   4096
#define INDIM  256
#define OUTDIM 256
#define NC     8
#define KDIM   (INDIM * NC)      // 2048
#define KSPLIT 2
#define KHALF  (KDIM / KSPLIT)   // 1024

// ---------------- scratch (static device globals; no allocations) ----------
__device__ __nv_bfloat16 g_Bh[(size_t)OUTDIM * KDIM];      // 1 MB  B, [o][k]
__device__ float g_part[(size_t)KSPLIT * BDIM * OUTDIM];   // 8 MB  partials
__device__ float g_rvp[KSPLIT * BDIM];                     // rv partials

// ---------------------------------------------------------------------------
// 1) B = W^T:  g_Bh[o][i*8+c] = bf16( spline_scale[i,o] * coefs[i,o,c] )
// ---------------------------------------------------------------------------
__global__ __launch_bounds__(256) void build_W_kernel(
    const float* __restrict__ coefs, const float* __restrict__ spline_scale) {
    int idx = blockIdx.x * 256 + threadIdx.x;  // i*256 + o
    int i = idx >> 8, o = idx & 255;
    float ss = spline_scale[idx];
    const float* cf = coefs + (size_t)idx * NC;
    uint4 uh;
    uint32_t* ph = (uint32_t*)&uh;
#pragma unroll
    for (int c = 0; c < 4; c++) {
        __nv_bfloat162 t = __floats2bfloat162_rn(ss * cf[2 * c], ss * cf[2 * c + 1]);
        ph[c] = *(uint32_t*)&t;
    }
    *(uint4*)&g_Bh[(size_t)o * KDIM + i * NC] = uh;
}

// ---------------------------------------------------------------------------
// 2) fused GEMM, single-pass bf16, split-K=2
//    CTA 64x64, BK=64, 128 threads (4 warps, warp tile 32x32)
// ---------------------------------------------------------------------------
#define BM 64
#define BN 64
#define BK 64
#define NTS (KHALF / BK)        // 16 k-chunks per split

#define ROWB 144                // 128B data + 16B pad
#define TILE_B (64 * ROWB)      // 9216 per tile
// stage layout: A @0, B @TILE_B
#define STAGE_B (2 * TILE_B)    // 18432
#define GEMM_SMEM (2 * STAGE_B) // 36864

__device__ __forceinline__ uint32_t smem_u32(const void* p) {
    uint32_t a;
    asm("{ .reg .u64 t; cvta.to.shared.u64 t, %1; cvt.u32.u64 %0, t; }"
        : "=r"(a) : "l"(p));
    return a;
}
__device__ __forceinline__ void cp16(uint32_t s, const void* g) {
    asm volatile("cp.async.cg.shared.global [%0], [%1], 16;" :: "r"(s), "l"(g));
}
__device__ __forceinline__ void ldsm_x4(uint32_t* r, uint32_t addr) {
    asm volatile("ldmatrix.sync.aligned.m8n8.x4.shared.b16 {%0,%1,%2,%3}, [%4];"
                 : "=r"(r[0]), "=r"(r[1]), "=r"(r[2]), "=r"(r[3]) : "r"(addr));
}
__device__ __forceinline__ void mma_bf16(float* d, const uint32_t* a, const uint32_t* b) {
    asm volatile(
        "mma.sync.aligned.m16n8k16.row.col.f32.bf16.bf16.f32 "
        "{%0,%1,%2,%3}, {%4,%5,%6,%7}, {%8,%9}, {%0,%1,%2,%3};"
        : "+f"(d[0]), "+f"(d[1]), "+f"(d[2]), "+f"(d[3])
        : "r"(a[0]), "r"(a[1]), "r"(a[2]), "r"(a[3]), "r"(b[0]), "r"(b[1]));
}

// B prefetch: 64 rows x 128B -> 512 x 16B chunks / 128 threads
__device__ __forceinline__ void prefetch_B(uint32_t sbase, int k0, int n0, int tid) {
#pragma unroll
    for (int p = 0; p < 4; ++p) {
        int idx = p * 128 + tid;           // 0..511
        int r = idx >> 3, c = idx & 7;
        cp16(sbase + TILE_B + r * ROWB + c * 16,
             g_Bh + (size_t)(n0 + r) * KDIM + k0 + c * 8);
    }
    asm volatile("cp.async.commit_group;" ::: "memory");
}

// A compute: 64 rows x 8 i-values; each thread does 4 (b,i) pairs
__device__ __forceinline__ void compute_A(
    char* abase, int i, int m0, const float* __restrict__ x,
    const float* __restrict__ resid_scale, float* rv_acc,
    float alpha, const float* r1, const float* r2, int tid) {
    const float rs = resid_scale[i];
#pragma unroll
    for (int p = 0; p < 4; ++p) {
        int b = p * 16 + (tid >> 3);
        float t = tanhf(x[(size_t)(m0 + b) * INDIM + i]);
        rv_acc[p] += rs * t;

        float pr[NC];
        pr[0] = 1.0f;
        pr[1] = (alpha + 1.0f) + (alpha + alpha + 2.0f) * (t - 1.0f) * 0.5f;
#pragma unroll
        for (int n = 2; n < NC; n++)
            pr[n] = r1[n] * t * pr[n - 1] - r2[n] * pr[n - 2];

        uint4 uh;
        uint32_t* ph = (uint32_t*)&uh;
#pragma unroll
        for (int c = 0; c < 4; c++) {
            __nv_bfloat162 t2 = __floats2bfloat162_rn(pr[2 * c], pr[2 * c + 1]);
            ph[c] = *(uint32_t*)&t2;
        }
        *(uint4*)(abase + b * ROWB + (tid & 7) * 16) = uh;
    }
}

__global__ __launch_bounds__(128, 5) void gemm_fused(
    const float* __restrict__ x, const float* __restrict__ resid_scale,
    const float* __restrict__ aat) {
    extern __shared__ char smem[];
    const int tid  = threadIdx.x;
    const int wid  = tid >> 5;
    const int lane = tid & 31;
    const int m0   = blockIdx.x * BM;
    const int n0   = blockIdx.y * BN;
    const int z    = blockIdx.z;
    const int mbase = (wid & 1) * 32;
    const int nbase = (wid >> 1) * 32;
    const uint32_t sb = smem_u32(smem);

    // recurrence coefficients computed locally (no prep kernel)
    const float alpha = tanhf(__ldg(aat));
    float r1[NC], r2[NC];
#pragma unroll
    for (int n = 2; n < NC; n++) {
        float c = 2.0f * n + 2.0f * alpha;
        float A = 2.0f * n * (n + 2.0f * alpha) * (c - 2.0f);
        r1[n] = (c - 1.0f) * c * (c - 2.0f) / A;
        r2[n] = 2.0f * (n + alpha - 1.0f) * (n + alpha - 1.0f) * c / A;
    }

    float acc[2][4][4];
#pragma unroll
    for (int i = 0; i < 2; i++)
#pragma unroll
        for (int j = 0; j < 4; j++)
#pragma unroll
            for (int r = 0; r < 4; r++) acc[i][j][r] = 0.0f;
    float rv_acc[4] = {0.f, 0.f, 0.f, 0.f};

    // ldmatrix per-lane address pieces (mapping verified in R3/R4)
    const int g  = lane >> 3;
    const int lr = lane & 7;
    const int a_row_off = lr + ((g & 1) ? 8 : 0);
    const int kb_off    = (g >= 2) ? 16 : 0;

    const int ibase = z * (KHALF / NC);   // i-range of this split
    const int kbase = z * KHALF;

    // prologue
    compute_A(smem, ibase + (tid & 7), m0, x, resid_scale, rv_acc,
              alpha, r1, r2, tid);
    prefetch_B(sb, kbase, n0, tid);
    prefetch_B(sb + STAGE_B, kbase + BK, n0, tid);
    asm volatile("cp.async.wait_group 1;" ::: "memory");
    __syncthreads();

    for (int kt = 0; kt < NTS; ++kt) {
        const int s = kt & 1;
        const uint32_t st = sb + s * STAGE_B;

#pragma unroll
        for (int ks = 0; ks < 4; ++ks) {
            uint32_t a[2][4], b[4][2];
#pragma unroll
            for (int mf = 0; mf < 2; ++mf) {
                uint32_t row = mbase + mf * 16 + a_row_off;
                ldsm_x4(a[mf], st + row * ROWB + ks * 32 + kb_off);
            }
#pragma unroll
            for (int np = 0; np < 2; ++np) {
                uint32_t row = nbase + np * 16 + lr + ((g >= 2) ? 8 : 0);
                uint32_t kb2 = ks * 32 + ((g & 1) ? 16 : 0);
                uint32_t r4[4];
                ldsm_x4(r4, st + TILE_B + row * ROWB + kb2);
                b[2 * np][0] = r4[0];     b[2 * np][1] = r4[1];
                b[2 * np + 1][0] = r4[2]; b[2 * np + 1][1] = r4[3];
            }
#pragma unroll
            for (int mf = 0; mf < 2; ++mf)
#pragma unroll
                for (int nf = 0; nf < 4; ++nf)
                    mma_bf16(acc[mf][nf], a[mf], b[nf]);
        }
        __syncthreads();   // all warps done reading stage s

        if (kt + 1 < NTS) {
            compute_A(smem + (s ^ 1) * STAGE_B, ibase + (kt + 1) * 8 + (tid & 7),
                      m0, x, resid_scale, rv_acc, alpha, r1, r2, tid);
            if (kt + 2 < NTS) {
                prefetch_B(st, kbase + (kt + 2) * BK, n0, tid);
                asm volatile("cp.async.wait_group 1;" ::: "memory");
            } else {
                asm volatile("cp.async.wait_group 0;" ::: "memory");
            }
            __syncthreads();
        }
    }

    // rv partial: reduce 8 lanes (same b); ALL warps store their disjoint
    // tid>>3 slots (0..15) — this was the R5 bug (extra wid==0 guard).
    if (blockIdx.y == 0) {
#pragma unroll
        for (int p = 0; p < 4; ++p) {
            float v = rv_acc[p];
            v += __shfl_xor_sync(0xffffffffu, v, 1);
            v += __shfl_xor_sync(0xffffffffu, v, 2);
            v += __shfl_xor_sync(0xffffffffu, v, 4);
            if ((lane & 7) == 0)
                g_rvp[z * BDIM + m0 + p * 16 + (tid >> 3)] = v;
        }
    }

    // write partial tile
    float* dst = g_part + (size_t)z * BDIM * OUTDIM;
    const int l4 = lane >> 2, l2 = (lane & 3) * 2;
#pragma unroll
    for (int mf = 0; mf < 2; ++mf) {
        int m = m0 + mbase + mf * 16 + l4;
#pragma unroll
        for (int nf = 0; nf < 4; ++nf) {
            int n = n0 + nbase + nf * 8 + l2;
            *(float2*)&dst[(size_t)m * OUTDIM + n] =
                make_float2(acc[mf][nf][0], acc[mf][nf][1]);
            *(float2*)&dst[(size_t)(m + 8) * OUTDIM + n] =
                make_float2(acc[mf][nf][2], acc[mf][nf][3]);
        }
    }
}

// ---------------------------------------------------------------------------
// 3) combine: out = (part0 + part1 + rv0 + rv1) / IN
// ---------------------------------------------------------------------------
__global__ __launch_bounds__(256) void combine_kernel(float* __restrict__ out) {
    int idx = blockIdx.x * 256 + threadIdx.x;   // float4 index
    int m = idx >> 6, c4 = (idx & 63) * 4;
    size_t o0 = (size_t)m * OUTDIM + c4;
    float4 a = *(float4*)&g_part[o0];
    float4 b = *(float4*)&g_part[(size_t)BDIM * OUTDIM + o0];
    float rv = g_rvp[m] + g_rvp[BDIM + m];
    const float s = 1.0f / (float)INDIM;
    float4 o;
    o.x = (a.x + b.x + rv) * s;
    o.y = (a.y + b.y + rv) * s;
    o.z = (a.z + b.z + rv) * s;
    o.w = (a.w + b.w + rv) * s;
    *(float4*)&out[o0] = o;
}

// ---------------------------------------------------------------------------
extern "C" void kernel_launch(void* const* d_in, const int* in_sizes, int n_in,
                              void* d_out, int out_size) {
    const float *x = nullptr, *coefs = nullptr, *aat = nullptr;
    const float *resid_scale = nullptr, *spline_scale = nullptr;
    for (int i = 0; i < n_in; i++) {
        switch (in_sizes[i]) {
            case BDIM * INDIM:        x            = (const float*)d_in[i]; break;
            case INDIM * OUTDIM * NC: coefs        = (const float*)d_in[i]; break;
            case 1:                   aat          = (const float*)d_in[i]; break;
            case INDIM:               resid_scale  = (const float*)d_in[i]; break;
            case INDIM * OUTDIM:      spline_scale = (const float*)d_in[i]; break;
            default: break;
        }
    }
    float* out = (float*)d_out;

    cudaFuncSetAttribute(gemm_fused, cudaFuncAttributeMaxDynamicSharedMemorySize, GEMM_SMEM);

    build_W_kernel<<<(INDIM * OUTDIM) / 256, 256>>>(coefs, spline_scale);
    dim3 grid(BDIM / BM, OUTDIM / BN, KSPLIT);
    gemm_fused<<<grid, 128, GEMM_SMEM>>>(x, resid_scale, aat);
    combine_kernel<<<(BDIM * OUTDIM / 4) / 256, 256>>>(out);
}